// round 1
// baseline (speedup 1.0000x reference)
#include <cuda_runtime.h>
#include <cuda_bf16.h>
#include <math.h>

// ---------------------------------------------------------------------------
// LSAMCell: B=1024, INPUT_DIM=1024, D_MODEL=1024, NHEAD=16, D_HEAD=64
//   xh = [x | h]                       [1024, 2048]
//   qkv = xh @ Wqkv + b                [1024, 3072]   (big fp32 GEMM)
//   w = sigmoid(xh @ Ww + b), r = ...  [1024, 16] each
//   per (b, n): q/k unitnorm, v_r = AM k, vp = w (v - v_r),
//               AM_new = AM + k vp^T (outer: AM_new[v][q] = AM + k[q] vp[v])
//               h_new  = (AM_new q) * r = (AM q + vp (k.q)) * r
// Output: d_out[0 .. 1048576)   = h_new  [1024,1024]
//         d_out[1048576 .. end) = AM_new [1024,16,64,64]
// ---------------------------------------------------------------------------

#define B_      1024
#define K_      2048
#define NQKV    3072
#define NHEAD_  16
#define DHEAD   64

// scratch (device globals: allocation-free rule)
__device__ float g_qkv[B_ * NQKV];   // 12 MB
__device__ float g_wr [B_ * 32];     // sigmoid(w) cols 0..15, sigmoid(r) cols 16..31

// ---------------------------------------------------------------------------
// Kernel A: fp32 SGEMM  C[1024,3072] = [x|h] @ Wqkv + bias
// 128x128 tile, BK=16, 256 threads, 8x8 per thread.
// ---------------------------------------------------------------------------
__global__ __launch_bounds__(256) void sgemm_qkv(
    const float* __restrict__ X, const float* __restrict__ H,
    const float* __restrict__ W, const float* __restrict__ bias)
{
    __shared__ float As[16][128];   // [k][m]
    __shared__ float Bs[16][128];   // [k][n]

    const int bn = blockIdx.x * 128;
    const int bm = blockIdx.y * 128;
    const int tid = threadIdx.x;
    const int tx = tid & 15;        // 0..15  -> n
    const int ty = tid >> 4;        // 0..15  -> m

    float acc[8][8];
    #pragma unroll
    for (int i = 0; i < 8; i++)
        #pragma unroll
        for (int j = 0; j < 8; j++) acc[i][j] = 0.0f;

    for (int k0 = 0; k0 < K_; k0 += 16) {
        // ---- load A tile (128 rows x 16 k), transposed into As[k][m] ----
        #pragma unroll
        for (int it = 0; it < 2; it++) {
            int f   = tid + it * 256;          // 0..511 float4 slots
            int row = f >> 2;                  // 0..127
            int c4  = f & 3;                   // 0..3
            int gk  = k0 + c4 * 4;
            int gm  = bm + row;
            const float* src = (gk < 1024) ? (X + (size_t)gm * 1024 + gk)
                                           : (H + (size_t)gm * 1024 + (gk - 1024));
            float4 a4 = *reinterpret_cast<const float4*>(src);
            As[c4 * 4 + 0][row] = a4.x;
            As[c4 * 4 + 1][row] = a4.y;
            As[c4 * 4 + 2][row] = a4.z;
            As[c4 * 4 + 3][row] = a4.w;
        }
        // ---- load B tile (16 k x 128 n) ----
        #pragma unroll
        for (int it = 0; it < 2; it++) {
            int f   = tid + it * 256;
            int kk  = f >> 5;                  // 0..15
            int c4  = f & 31;                  // 0..31
            float4 b4 = *reinterpret_cast<const float4*>(
                W + (size_t)(k0 + kk) * NQKV + bn + c4 * 4);
            *reinterpret_cast<float4*>(&Bs[kk][c4 * 4]) = b4;
        }
        __syncthreads();

        #pragma unroll
        for (int kk = 0; kk < 16; kk++) {
            float a[8], b[8];
            *reinterpret_cast<float4*>(&a[0]) = *reinterpret_cast<const float4*>(&As[kk][ty * 8 + 0]);
            *reinterpret_cast<float4*>(&a[4]) = *reinterpret_cast<const float4*>(&As[kk][ty * 8 + 4]);
            *reinterpret_cast<float4*>(&b[0]) = *reinterpret_cast<const float4*>(&Bs[kk][tx * 8 + 0]);
            *reinterpret_cast<float4*>(&b[4]) = *reinterpret_cast<const float4*>(&Bs[kk][tx * 8 + 4]);
            #pragma unroll
            for (int i = 0; i < 8; i++)
                #pragma unroll
                for (int j = 0; j < 8; j++)
                    acc[i][j] = fmaf(a[i], b[j], acc[i][j]);
        }
        __syncthreads();
    }

    // epilogue: + bias, store
    #pragma unroll
    for (int i = 0; i < 8; i++) {
        int gm = bm + ty * 8 + i;
        #pragma unroll
        for (int j4 = 0; j4 < 8; j4 += 4) {
            int gn = bn + tx * 8 + j4;
            float4 o;
            o.x = acc[i][j4 + 0] + bias[gn + 0];
            o.y = acc[i][j4 + 1] + bias[gn + 1];
            o.z = acc[i][j4 + 2] + bias[gn + 2];
            o.w = acc[i][j4 + 3] + bias[gn + 3];
            *reinterpret_cast<float4*>(&g_qkv[(size_t)gm * NQKV + gn]) = o;
        }
    }
}

// ---------------------------------------------------------------------------
// Kernel C: w/r tiny GEMM + sigmoid. Block handles 4 batch rows, 256 threads.
// warp g (0..7): columns 4g..4g+3 of [Ww | Wr] (g<4 -> Ww, else Wr), all 4 rows.
// ---------------------------------------------------------------------------
__global__ __launch_bounds__(256) void small_gemm_wr(
    const float* __restrict__ X, const float* __restrict__ H,
    const float* __restrict__ Ww, const float* __restrict__ Wb,
    const float* __restrict__ Wr, const float* __restrict__ Rb)
{
    __shared__ float xs[4][2048];   // 32 KB
    const int r0  = blockIdx.x * 4;
    const int tid = threadIdx.x;

    #pragma unroll
    for (int r = 0; r < 4; r++)
        for (int e = tid; e < 2048; e += 256)
            xs[r][e] = (e < 1024) ? X[(size_t)(r0 + r) * 1024 + e]
                                  : H[(size_t)(r0 + r) * 1024 + (e - 1024)];
    __syncthreads();

    const int warp = tid >> 5, lane = tid & 31;
    const float* Wsel = (warp < 4) ? Ww : Wr;
    const float* Bsel = (warp < 4) ? Wb : Rb;
    const int g = (warp & 3) * 4;   // column base in [0,16)

    float acc[4][4];
    #pragma unroll
    for (int r = 0; r < 4; r++)
        #pragma unroll
        for (int c = 0; c < 4; c++) acc[r][c] = 0.0f;

    for (int k = lane; k < 2048; k += 32) {
        float4 wv = *reinterpret_cast<const float4*>(&Wsel[(size_t)k * 16 + g]);
        #pragma unroll
        for (int r = 0; r < 4; r++) {
            float xv = xs[r][k];
            acc[r][0] = fmaf(xv, wv.x, acc[r][0]);
            acc[r][1] = fmaf(xv, wv.y, acc[r][1]);
            acc[r][2] = fmaf(xv, wv.z, acc[r][2]);
            acc[r][3] = fmaf(xv, wv.w, acc[r][3]);
        }
    }
    #pragma unroll
    for (int r = 0; r < 4; r++)
        #pragma unroll
        for (int c = 0; c < 4; c++)
            #pragma unroll
            for (int o = 16; o; o >>= 1)
                acc[r][c] += __shfl_xor_sync(0xffffffffu, acc[r][c], o);

    if (lane == 0) {
        const int colbase = ((warp < 4) ? 0 : 16) + g;
        #pragma unroll
        for (int r = 0; r < 4; r++)
            #pragma unroll
            for (int c = 0; c < 4; c++) {
                float v = acc[r][c] + Bsel[g + c];
                g_wr[(size_t)(r0 + r) * 32 + colbase + c] = 1.0f / (1.0f + expf(-v));
            }
    }
}

// ---------------------------------------------------------------------------
// Kernel B: per-(b,head) AM update. 16384 blocks x 128 threads.
// ---------------------------------------------------------------------------
__global__ __launch_bounds__(128) void am_update(
    const float* __restrict__ AM, float* __restrict__ hout, float* __restrict__ AMout)
{
    __shared__ float AMs[64 * 65];
    __shared__ float qv[64], kv[64], vv[64], vp[64];
    __shared__ float scq, sck, kqdot;

    const int bh = blockIdx.x;
    const int b  = bh >> 4;
    const int n  = bh & 15;
    const int tid = threadIdx.x;

    const float* amg = AM + (size_t)bh * 4096;
    for (int e = tid; e < 4096; e += 128)
        AMs[(e >> 6) * 65 + (e & 63)] = amg[e];

    if (tid < 64) {
        const float* base = g_qkv + (size_t)b * NQKV + n * DHEAD + tid;
        qv[tid] = base[0];
        kv[tid] = base[1024];
        vv[tid] = base[2048];
    }
    __syncthreads();

    if (tid < 32) {
        float s = qv[tid] * qv[tid] + qv[tid + 32] * qv[tid + 32];
        #pragma unroll
        for (int o = 16; o; o >>= 1) s += __shfl_xor_sync(0xffffffffu, s, o);
        if (tid == 0) scq = 1.0f / fmaxf(sqrtf(s), 1e-12f);
    } else if (tid < 64) {
        int l = tid - 32;
        float s = kv[l] * kv[l] + kv[l + 32] * kv[l + 32];
        #pragma unroll
        for (int o = 16; o; o >>= 1) s += __shfl_xor_sync(0xffffffffu, s, o);
        if (l == 0) sck = 1.0f / fmaxf(sqrtf(s), 1e-12f);
    }
    __syncthreads();
    if (tid < 64) { qv[tid] *= scq; kv[tid] *= sck; }
    __syncthreads();
    if (tid < 32) {
        float s = kv[tid] * qv[tid] + kv[tid + 32] * qv[tid + 32];
        #pragma unroll
        for (int o = 16; o; o >>= 1) s += __shfl_xor_sync(0xffffffffu, s, o);
        if (tid == 0) kqdot = s;
    }
    __syncthreads();

    const float w = g_wr[(size_t)b * 32 + n];
    const float r = g_wr[(size_t)b * 32 + 16 + n];

    if (tid < 64) {
        const float* row = &AMs[tid * 65];
        float dk = 0.0f, dq = 0.0f;
        #pragma unroll 16
        for (int q = 0; q < 64; q++) {
            float a = row[q];
            dk = fmaf(a, kv[q], dk);
            dq = fmaf(a, qv[q], dq);
        }
        float vpv = w * (vv[tid] - dk);
        vp[tid] = vpv;
        hout[(size_t)b * 1024 + n * DHEAD + tid] = (dq + vpv * kqdot) * r;
    }
    __syncthreads();

    float* og = AMout + (size_t)bh * 4096;
    for (int e = tid; e < 4096; e += 128) {
        int v = e >> 6, q = e & 63;
        og[e] = AMs[v * 65 + q] + kv[q] * vp[v];
    }
}

// ---------------------------------------------------------------------------
extern "C" void kernel_launch(void* const* d_in, const int* in_sizes, int n_in,
                              void* d_out, int out_size)
{
    const float* x      = (const float*)d_in[0];
    const float* h      = (const float*)d_in[1];
    const float* AM     = (const float*)d_in[2];
    const float* Wqkv_w = (const float*)d_in[3];
    const float* Wqkv_b = (const float*)d_in[4];
    const float* Ww_w   = (const float*)d_in[5];
    const float* Ww_b   = (const float*)d_in[6];
    const float* Wr_w   = (const float*)d_in[7];
    const float* Wr_b   = (const float*)d_in[8];

    float* out   = (float*)d_out;
    float* h_new = out;                       // [1024*1024]
    float* AM_new = out + (size_t)B_ * 1024;  // [1024*16*64*64]

    sgemm_qkv<<<dim3(NQKV / 128, B_ / 128), 256>>>(x, h, Wqkv_w, Wqkv_b);
    small_gemm_wr<<<B_ / 4, 256>>>(x, h, Ww_w, Ww_b, Wr_w, Wr_b);
    am_update<<<B_ * NHEAD_, 128>>>(AM, h_new, AM_new);
}

// round 3
// speedup vs baseline: 1.7221x; 1.7221x over previous
#include <cuda_runtime.h>
#include <cuda_bf16.h>
#include <math.h>
#include <cstdint>

// ---------------------------------------------------------------------------
// LSAMCell — Round 3: split-bf16 GEMM on legacy mma.sync (sm_80 baseline ISA;
// tcgen05 is unavailable because the build lowers via .target sm_103).
//   A'[1024,6144] = [Ah | Al | Ah] bf16 (M-major)
//   W'[3072,6144] = [Wh | Wh | Wl] bf16 (N rows, K cols = B^T layout)
//   qkv = A' @ W'^T + bias   (fp32 accum; missing Al*Wl term ~2^-18)
// ---------------------------------------------------------------------------

#define B_      1024
#define K_      2048
#define NQKV    3072
#define KTOT    6144
#define NHEAD_  16
#define DHEAD   64

// GEMM tiling
#define TM      128
#define TN      128
#define BK      32
#define STAGES  3
#define NST     (KTOT / BK)        // 192
#define PITCH   80                 // bytes per tile row (64B data + skew)
#define TILE_B  (128 * PITCH)      // 10240 bytes per operand tile
#define STAGE_BYTES (2 * TILE_B)   // 20480
#define SMEM_TOTAL  (STAGES * STAGE_BYTES)  // 61440

// device scratch (allocation-free rule)
__device__ float g_qkv[B_ * NQKV];                       // 12 MB
__device__ float g_wr [B_ * 32];
__device__ __align__(16) __nv_bfloat16 g_A[B_ * KTOT];   // 12.6 MB
__device__ __align__(16) __nv_bfloat16 g_W[NQKV * KTOT]; // 37.7 MB

// ---------------------------------------------------------------------------
__device__ __forceinline__ uint32_t smem_u32(const void* p) {
    uint32_t a;
    asm("{ .reg .u64 t; cvta.to.shared.u64 t, %1; cvt.u32.u64 %0, t; }" : "=r"(a) : "l"(p));
    return a;
}
__device__ __forceinline__ void cp16(uint32_t dst, const void* src) {
    asm volatile("cp.async.cg.shared.global [%0], [%1], 16;" :: "r"(dst), "l"(src));
}
#define CP_COMMIT() asm volatile("cp.async.commit_group;" ::: "memory")
#define CP_WAIT(n)  asm volatile("cp.async.wait_group %0;" :: "n"(n) : "memory")

__device__ __forceinline__ void ldsm_x4(uint32_t (&r)[4], uint32_t addr) {
    asm volatile("ldmatrix.sync.aligned.m8n8.x4.shared.b16 {%0,%1,%2,%3}, [%4];"
                 : "=r"(r[0]), "=r"(r[1]), "=r"(r[2]), "=r"(r[3]) : "r"(addr));
}
__device__ __forceinline__ void mma16816(
    float (&c)[4], const uint32_t (&a)[4], uint32_t b0, uint32_t b1) {
    asm volatile(
        "mma.sync.aligned.m16n8k16.row.col.f32.bf16.bf16.f32 "
        "{%0,%1,%2,%3}, {%4,%5,%6,%7}, {%8,%9}, {%0,%1,%2,%3};"
        : "+f"(c[0]), "+f"(c[1]), "+f"(c[2]), "+f"(c[3])
        : "r"(a[0]), "r"(a[1]), "r"(a[2]), "r"(a[3]), "r"(b0), "r"(b1));
}

// ---------------------------------------------------------------------------
// conversion kernels: fp32 -> split bf16
// ---------------------------------------------------------------------------
__global__ __launch_bounds__(256) void conv_A(
    const float* __restrict__ X, const float* __restrict__ H)
{
    int f = blockIdx.x * 256 + threadIdx.x;     // float4 id, 524288 total
    int m = f >> 9;
    int k = (f & 511) * 4;
    const float* src = (k < 1024) ? (X + (size_t)m * 1024 + k)
                                  : (H + (size_t)m * 1024 + (k - 1024));
    float4 v = *reinterpret_cast<const float4*>(src);
    __nv_bfloat16 hi[4], lo[4];
    float vv[4] = {v.x, v.y, v.z, v.w};
    #pragma unroll
    for (int i = 0; i < 4; i++) {
        hi[i] = __float2bfloat16_rn(vv[i]);
        lo[i] = __float2bfloat16_rn(vv[i] - __bfloat162float(hi[i]));
    }
    size_t base = (size_t)m * KTOT + k;
    *reinterpret_cast<uint2*>(&g_A[base])        = *reinterpret_cast<uint2*>(hi);
    *reinterpret_cast<uint2*>(&g_A[base + 2048]) = *reinterpret_cast<uint2*>(lo);
    *reinterpret_cast<uint2*>(&g_A[base + 4096]) = *reinterpret_cast<uint2*>(hi);
}

__global__ __launch_bounds__(256) void conv_W(const float* __restrict__ W)
{
    __shared__ float tile[32][33];
    const int n0 = blockIdx.x * 32;
    const int k0 = blockIdx.y * 32;
    const int t  = threadIdx.x;
    const int tx = t & 31, ty = t >> 5;
    #pragma unroll
    for (int i = 0; i < 4; i++)
        tile[ty + 8 * i][tx] = W[(size_t)(k0 + ty + 8 * i) * NQKV + n0 + tx];
    __syncthreads();
    #pragma unroll
    for (int i = 0; i < 4; i++) {
        int nl = ty + 8 * i, kl = tx;
        float v = tile[kl][nl];
        __nv_bfloat16 hi = __float2bfloat16_rn(v);
        __nv_bfloat16 lo = __float2bfloat16_rn(v - __bfloat162float(hi));
        size_t base = (size_t)(n0 + nl) * KTOT + (k0 + kl);
        g_W[base]        = hi;
        g_W[base + 2048] = hi;
        g_W[base + 4096] = lo;
    }
}

// ---------------------------------------------------------------------------
// GEMM: g_qkv[1024,3072] = A' @ W'^T + bias
// CTA 128x128, BK=32, 3-stage cp.async, 8 warps (4m x 2n), warp tile 32x64.
// ---------------------------------------------------------------------------
__device__ __forceinline__ void load_stage(uint32_t sb, int t, int bm, int bn)
{
    const int tid = threadIdx.x;
    const uint32_t base = sb + (t % STAGES) * STAGE_BYTES;
    const __nv_bfloat16* gA = g_A + (size_t)bm * KTOT + t * BK;
    const __nv_bfloat16* gB = g_W + (size_t)bn * KTOT + t * BK;
    // 512 chunks of 16B each for A and B; 256 threads x 2 each
    #pragma unroll
    for (int i = 0; i < 2; i++) {
        int c = tid + i * 256;
        int row = c >> 2, cc = c & 3;
        cp16(base + row * PITCH + cc * 16, gA + (size_t)row * KTOT + cc * 8);
    }
    #pragma unroll
    for (int i = 0; i < 2; i++) {
        int c = tid + i * 256;
        int row = c >> 2, cc = c & 3;
        cp16(base + TILE_B + row * PITCH + cc * 16, gB + (size_t)row * KTOT + cc * 8);
    }
    CP_COMMIT();
}

__global__ __launch_bounds__(256, 2) void gemm_qkv_mma(const float* __restrict__ bias)
{
    extern __shared__ char smem[];
    const uint32_t sb = smem_u32(smem);
    const int tid  = threadIdx.x;
    const int lane = tid & 31, wid = tid >> 5;
    const int wm = (wid & 3) * 32;      // warp m offset in tile
    const int wn = (wid >> 2) * 64;     // warp n offset in tile
    const int bn = blockIdx.x * TN;
    const int bm = blockIdx.y * TM;

    // lane-derived ldmatrix addressing
    const int grp = lane >> 3;
    const int l7  = lane & 7;
    const int arow = wm + (grp & 1) * 8 + l7;   // + mf*16
    const int achk = grp >> 1;                  // + 2*ks
    const int brow = wn + (grp >> 1) * 8 + l7;  // + nf*16
    const int bchk = grp & 1;                   // + 2*ks

    float acc[2][8][4];
    #pragma unroll
    for (int i = 0; i < 2; i++)
        #pragma unroll
        for (int j = 0; j < 8; j++)
            #pragma unroll
            for (int l = 0; l < 4; l++) acc[i][j][l] = 0.0f;

    load_stage(sb, 0, bm, bn);
    load_stage(sb, 1, bm, bn);

    for (int s = 0; s < NST; s++) {
        if (s + 2 < NST) { load_stage(sb, s + 2, bm, bn); CP_WAIT(2); }
        else if (s + 1 < NST) { CP_WAIT(1); }
        else { CP_WAIT(0); }
        __syncthreads();

        const uint32_t abase = sb + (s % STAGES) * STAGE_BYTES;
        const uint32_t bbase = abase + TILE_B;

        #pragma unroll
        for (int ks = 0; ks < 2; ks++) {
            uint32_t a[2][4], b[4][4];
            #pragma unroll
            for (int mf = 0; mf < 2; mf++)
                ldsm_x4(a[mf], abase + (arow + mf * 16) * PITCH + (achk + 2 * ks) * 16);
            #pragma unroll
            for (int nf = 0; nf < 4; nf++)
                ldsm_x4(b[nf], bbase + (brow + nf * 16) * PITCH + (bchk + 2 * ks) * 16);
            #pragma unroll
            for (int mf = 0; mf < 2; mf++)
                #pragma unroll
                for (int nf = 0; nf < 4; nf++) {
                    mma16816(acc[mf][nf * 2 + 0], a[mf], b[nf][0], b[nf][1]);
                    mma16816(acc[mf][nf * 2 + 1], a[mf], b[nf][2], b[nf][3]);
                }
        }
        __syncthreads();
    }

    // epilogue: c[mf][ng][.]: thread holds (m = lane/4 (+8), n = (lane&3)*2, +1)
    const int q = lane >> 2;
    const int n2 = (lane & 3) * 2;
    #pragma unroll
    for (int ng = 0; ng < 8; ng++) {
        const int gn = bn + wn + ng * 8 + n2;
        const float bx = bias[gn], by = bias[gn + 1];
        #pragma unroll
        for (int mf = 0; mf < 2; mf++) {
            const int gm = bm + wm + mf * 16 + q;
            float2 lo = { acc[mf][ng][0] + bx, acc[mf][ng][1] + by };
            float2 hi = { acc[mf][ng][2] + bx, acc[mf][ng][3] + by };
            *reinterpret_cast<float2*>(&g_qkv[(size_t)gm * NQKV + gn])       = lo;
            *reinterpret_cast<float2*>(&g_qkv[(size_t)(gm + 8) * NQKV + gn]) = hi;
        }
    }
}

// ---------------------------------------------------------------------------
// small GEMM for w/r (unchanged)
// ---------------------------------------------------------------------------
__global__ __launch_bounds__(256) void small_gemm_wr(
    const float* __restrict__ X, const float* __restrict__ H,
    const float* __restrict__ Ww, const float* __restrict__ Wb,
    const float* __restrict__ Wr, const float* __restrict__ Rb)
{
    __shared__ float xs[4][2048];
    const int r0  = blockIdx.x * 4;
    const int tid = threadIdx.x;
    #pragma unroll
    for (int r = 0; r < 4; r++)
        for (int e = tid; e < 2048; e += 256)
            xs[r][e] = (e < 1024) ? X[(size_t)(r0 + r) * 1024 + e]
                                  : H[(size_t)(r0 + r) * 1024 + (e - 1024)];
    __syncthreads();

    const int warp = tid >> 5, lane = tid & 31;
    const float* Wsel = (warp < 4) ? Ww : Wr;
    const float* Bsel = (warp < 4) ? Wb : Rb;
    const int g = (warp & 3) * 4;

    float acc[4][4];
    #pragma unroll
    for (int r = 0; r < 4; r++)
        #pragma unroll
        for (int c = 0; c < 4; c++) acc[r][c] = 0.0f;

    for (int k = lane; k < 2048; k += 32) {
        float4 wv = *reinterpret_cast<const float4*>(&Wsel[(size_t)k * 16 + g]);
        #pragma unroll
        for (int r = 0; r < 4; r++) {
            float xv = xs[r][k];
            acc[r][0] = fmaf(xv, wv.x, acc[r][0]);
            acc[r][1] = fmaf(xv, wv.y, acc[r][1]);
            acc[r][2] = fmaf(xv, wv.z, acc[r][2]);
            acc[r][3] = fmaf(xv, wv.w, acc[r][3]);
        }
    }
    #pragma unroll
    for (int r = 0; r < 4; r++)
        #pragma unroll
        for (int c = 0; c < 4; c++)
            #pragma unroll
            for (int o = 16; o; o >>= 1)
                acc[r][c] += __shfl_xor_sync(0xffffffffu, acc[r][c], o);

    if (lane == 0) {
        const int colbase = ((warp < 4) ? 0 : 16) + g;
        #pragma unroll
        for (int r = 0; r < 4; r++)
            #pragma unroll
            for (int c = 0; c < 4; c++) {
                float v = acc[r][c] + Bsel[g + c];
                g_wr[(size_t)(r0 + r) * 32 + colbase + c] = 1.0f / (1.0f + expf(-v));
            }
    }
}

// ---------------------------------------------------------------------------
// per-(b,head) AM update (unchanged)
// ---------------------------------------------------------------------------
__global__ __launch_bounds__(128) void am_update(
    const float* __restrict__ AM, float* __restrict__ hout, float* __restrict__ AMout)
{
    __shared__ float AMs[64 * 65];
    __shared__ float qv[64], kv[64], vv[64], vp[64];
    __shared__ float scq, sck, kqdot;

    const int bh = blockIdx.x;
    const int b  = bh >> 4;
    const int n  = bh & 15;
    const int tid = threadIdx.x;

    const float* amg = AM + (size_t)bh * 4096;
    for (int e = tid; e < 4096; e += 128)
        AMs[(e >> 6) * 65 + (e & 63)] = amg[e];

    if (tid < 64) {
        const float* base = g_qkv + (size_t)b * NQKV + n * DHEAD + tid;
        qv[tid] = base[0];
        kv[tid] = base[1024];
        vv[tid] = base[2048];
    }
    __syncthreads();

    if (tid < 32) {
        float s = qv[tid] * qv[tid] + qv[tid + 32] * qv[tid + 32];
        #pragma unroll
        for (int o = 16; o; o >>= 1) s += __shfl_xor_sync(0xffffffffu, s, o);
        if (tid == 0) scq = 1.0f / fmaxf(sqrtf(s), 1e-12f);
    } else if (tid < 64) {
        int l = tid - 32;
        float s = kv[l] * kv[l] + kv[l + 32] * kv[l + 32];
        #pragma unroll
        for (int o = 16; o; o >>= 1) s += __shfl_xor_sync(0xffffffffu, s, o);
        if (l == 0) sck = 1.0f / fmaxf(sqrtf(s), 1e-12f);
    }
    __syncthreads();
    if (tid < 64) { qv[tid] *= scq; kv[tid] *= sck; }
    __syncthreads();
    if (tid < 32) {
        float s = kv[tid] * qv[tid] + kv[tid + 32] * qv[tid + 32];
        #pragma unroll
        for (int o = 16; o; o >>= 1) s += __shfl_xor_sync(0xffffffffu, s, o);
        if (tid == 0) kqdot = s;
    }
    __syncthreads();

    const float w = g_wr[(size_t)b * 32 + n];
    const float r = g_wr[(size_t)b * 32 + 16 + n];

    if (tid < 64) {
        const float* row = &AMs[tid * 65];
        float dk = 0.0f, dq = 0.0f;
        #pragma unroll 16
        for (int q = 0; q < 64; q++) {
            float a = row[q];
            dk = fmaf(a, kv[q], dk);
            dq = fmaf(a, qv[q], dq);
        }
        float vpv = w * (vv[tid] - dk);
        vp[tid] = vpv;
        hout[(size_t)b * 1024 + n * DHEAD + tid] = (dq + vpv * kqdot) * r;
    }
    __syncthreads();

    float* og = AMout + (size_t)bh * 4096;
    for (int e = tid; e < 4096; e += 128) {
        int v = e >> 6, q = e & 63;
        og[e] = AMs[v * 65 + q] + kv[q] * vp[v];
    }
}

// ---------------------------------------------------------------------------
extern "C" void kernel_launch(void* const* d_in, const int* in_sizes, int n_in,
                              void* d_out, int out_size)
{
    const float* x      = (const float*)d_in[0];
    const float* h      = (const float*)d_in[1];
    const float* AM     = (const float*)d_in[2];
    const float* Wqkv_w = (const float*)d_in[3];
    const float* Wqkv_b = (const float*)d_in[4];
    const float* Ww_w   = (const float*)d_in[5];
    const float* Ww_b   = (const float*)d_in[6];
    const float* Wr_w   = (const float*)d_in[7];
    const float* Wr_b   = (const float*)d_in[8];

    float* out    = (float*)d_out;
    float* h_new  = out;
    float* AM_new = out + (size_t)B_ * 1024;

    cudaFuncSetAttribute(gemm_qkv_mma,
                         cudaFuncAttributeMaxDynamicSharedMemorySize, SMEM_TOTAL);

    conv_A<<<2048, 256>>>(x, h);
    conv_W<<<dim3(NQKV / 32, K_ / 32), 256>>>(Wqkv_w);
    gemm_qkv_mma<<<dim3(NQKV / TN, B_ / TM), 256, SMEM_TOTAL>>>(Wqkv_b);
    small_gemm_wr<<<B_ / 4, 256>>>(x, h, Ww_w, Ww_b, Wr_w, Wr_b);
    am_update<<<B_ * NHEAD_, 128>>>(AM, h_new, AM_new);
}